// round 17
// baseline (speedup 1.0000x reference)
#include <cuda_runtime.h>
#include <cuda_fp16.h>
#include <cstdint>

#define KDIM   256
#define BM     128
#define BN     256
#define BK     64

#define A_STAGE_BYTES (BM * BK * 2)            // 16384
#define A_TOTAL       (2 * A_STAGE_BYTES)      // 32768
#define B_CHUNK_BYTES (BN * BK * 2)            // 32768
#define B_TOTAL       (4 * B_CHUNK_BYTES)      // 131072
#define SMEM_MAIN     (A_TOTAL + B_TOTAL)      // 163840
#define SMEM_TOTAL    (SMEM_MAIN + 128)

__device__ unsigned g_ctr;     // dynamic tile counter (self-resetting)
__device__ unsigned g_done;    // CTA completion counter

// ---------------- helpers ----------------
__device__ __forceinline__ uint32_t smem_u32(const void* p) {
    uint32_t a;
    asm("{ .reg .u64 t; cvta.to.shared.u64 t, %1; cvt.u32.u64 %0, t; }" : "=r"(a) : "l"(p));
    return a;
}
#define LDSM4(r0, r1, r2, r3, a)                                                 \
    asm volatile("ldmatrix.sync.aligned.m8n8.x4.shared.b16 {%0,%1,%2,%3}, [%4];" \
                 : "=r"(r0), "=r"(r1), "=r"(r2), "=r"(r3) : "r"(a))

__device__ __forceinline__ void mma_fp16(float* d, const uint32_t* a,
                                         uint32_t b0, uint32_t b1) {
    asm volatile(
        "mma.sync.aligned.m16n8k16.row.col.f32.f16.f16.f32 "
        "{%0,%1,%2,%3}, {%4,%5,%6,%7}, {%8,%9}, {%0,%1,%2,%3};"
        : "+f"(d[0]), "+f"(d[1]), "+f"(d[2]), "+f"(d[3])
        : "r"(a[0]), "r"(a[1]), "r"(a[2]), "r"(a[3]), "r"(b0), "r"(b1));
}

// ---------------- main GEMM: persistent CTAs, B resident (built in-kernel),
//                  64x64 warp tile, dynamic tile scheduler ----------------
__global__ __launch_bounds__(256, 1)
void cp2d_fp16_kernel(const float* __restrict__ x, const float* __restrict__ W,
                      float* __restrict__ out, int NT) {
    extern __shared__ __align__(128) char smem[];
    const uint32_t sb = smem_u32(smem);
    int* nslot = (int*)(smem + SMEM_MAIN);

    const int tid  = threadIdx.x;
    const int lane = tid & 31;
    const int warp = tid >> 5;
    const int wm   = warp & 1;          // 2 warps along M (64 rows each)
    const int wn   = warp >> 1;         // 4 warps along N (64 cols each)

    // A mapping: 128 rows x 16 float4 per chunk, 8/thread  (round-15 exact)
    const int a_f   = tid & 15;
    const int a_row = tid >> 4;         // 0..15, rows += j*16

    // ldmatrix per-lane invariants
    const int la_row = (lane & 7) + ((lane >> 3) & 1) * 8;
    const int la_u   = lane >> 4;
    const int lb_row = (lane & 7) + ((lane >> 4) & 1) * 8;
    const int lb_u   = (lane >> 3) & 1;

    // ---- build resident B directly from W (fp32 [K,N] -> fp16 Wt[N,K], swizzled) ----
    {
        const int n = (warp << 5) + lane;          // 0..255, one n-row per thread
        const uint32_t swn = (uint32_t)(n & 7) << 4;
#pragma unroll
        for (int c = 0; c < 4; c++) {
            const uint32_t bBase = sb + A_TOTAL + (uint32_t)c * B_CHUNK_BYTES + n * 128;
#pragma unroll
            for (int u = 0; u < 8; u++) {
                float v[8];
#pragma unroll
                for (int j = 0; j < 8; j++)        // coalesced: lanes = consecutive n
                    v[j] = W[(c * 64 + u * 8 + j) * KDIM + n];
                __half2 h0 = __floats2half2_rn(v[0], v[1]);
                __half2 h1 = __floats2half2_rn(v[2], v[3]);
                __half2 h2 = __floats2half2_rn(v[4], v[5]);
                __half2 h3 = __floats2half2_rn(v[6], v[7]);
                uint32_t addr = bBase + (((uint32_t)u << 4) ^ swn);
                asm volatile("st.shared.v4.b32 [%0], {%1, %2, %3, %4};"
                             :: "r"(addr), "r"(*(uint32_t*)&h0), "r"(*(uint32_t*)&h1),
                                "r"(*(uint32_t*)&h2), "r"(*(uint32_t*)&h3));
            }
        }
    }

    // ---- grab first tile ----
    if (tid == 0) *nslot = (int)atomicAdd(&g_ctr, 1u);
    __syncthreads();                    // B + first tile id visible
    int cur = *nslot;

    float acc[4][8][4];
#pragma unroll
    for (int mt = 0; mt < 4; mt++)
#pragma unroll
        for (int nt = 0; nt < 8; nt++)
#pragma unroll
            for (int i = 0; i < 4; i++) acc[mt][nt][i] = 0.f;

    float4 rA[8];

    auto ldgA = [&](int t, int c) {
        const long m0 = (long)t * BM;
        const int k0 = c * BK;
#pragma unroll
        for (int j = 0; j < 8; j++)
            rA[j] = *(const float4*)(x + (m0 + a_row + j * 16) * KDIM + k0 + a_f * 4);
    };
    auto stsA = [&](int st) {          // st = 0/1
        const uint32_t aBase = sb + (uint32_t)st * A_STAGE_BYTES;
        const int u = a_f >> 1, off8 = (a_f & 1) * 8;
#pragma unroll
        for (int j = 0; j < 8; j++) {
            const int row = a_row + j * 16;
            uint32_t addr = aBase + row * 128 + ((u ^ (row & 7)) << 4) + off8;
            __half2 h0 = __floats2half2_rn(rA[j].x, rA[j].y);
            __half2 h1 = __floats2half2_rn(rA[j].z, rA[j].w);
            asm volatile("st.shared.v2.b32 [%0], {%1, %2};"
                         :: "r"(addr), "r"(rA ? *(uint32_t*)&h0 : 0u), "r"(*(uint32_t*)&h1));
        }
    };

    auto compute = [&](int st, int cb) {
        const uint32_t aBase = sb + (uint32_t)st * A_STAGE_BYTES;
        const uint32_t bBase = sb + A_TOTAL + (uint32_t)cb * B_CHUNK_BYTES;
#pragma unroll
        for (int ks = 0; ks < 4; ks++) {
            const int u0 = ks * 2;
            uint32_t b[4][4];
#pragma unroll
            for (int nt2 = 0; nt2 < 4; nt2++) {
                const int row = wn * 64 + nt2 * 16 + lb_row;
                uint32_t addr = bBase + row * 128 + (((u0 + lb_u) ^ (row & 7)) << 4);
                LDSM4(b[nt2][0], b[nt2][1], b[nt2][2], b[nt2][3], addr);
            }
#pragma unroll
            for (int mt = 0; mt < 4; mt++) {
                uint32_t a[4];
                const int row = wm * 64 + mt * 16 + la_row;
                uint32_t addr = aBase + row * 128 + (((u0 + la_u) ^ (row & 7)) << 4);
                LDSM4(a[0], a[1], a[2], a[3], addr);
#pragma unroll
                for (int nt2 = 0; nt2 < 4; nt2++)
#pragma unroll
                    for (int s = 0; s < 2; s++) {
                        const int nt = nt2 * 2 + s;
                        mma_fp16(acc[mt][nt], a, b[nt2][2 * s], b[nt2][2 * s + 1]);
                    }
            }
        }
    };

    if (cur < NT) {
        // ---- prologue: stage A chunk 0 of first tile ----
        ldgA(cur, 0);
        stsA(0);
        ldgA(cur, 1);
        __syncthreads();                // A stage0 visible

        int st = 0, c = 0, nxt = NT;
#pragma unroll 1
        while (true) {
            if (c == 0 && tid == 0) *nslot = (int)atomicAdd(&g_ctr, 1u);
            if (c == 1) nxt = *nslot;   // written at c==0, visible after its sync

            const bool more = (nxt < NT);
            // prefetch chunk c+1 (stsA) and chunk c+2 (ldgA); cross-tile at c>=2
            if (c < 3) {
                stsA(st ^ 1);                       // rA holds chunk c+1 (cur tile)
                if (c < 2)      ldgA(cur, c + 2);
                else if (more)  ldgA(nxt, 0);       // c==2: next tile chunk0
            } else if (more) {
                stsA(st ^ 1);                       // rA holds next tile chunk0
                ldgA(nxt, 1);
            }

            compute(st, c);

            if (c == 3) {
                // epilogue for cur tile
                const long m0 = (long)cur * BM;
                const int er = lane >> 2;
                const int ec = (lane & 3) * 2;
#pragma unroll
                for (int mt = 0; mt < 4; mt++) {
                    const long r0 = m0 + wm * 64 + mt * 16 + er;
#pragma unroll
                    for (int nt = 0; nt < 8; nt++) {
                        const int col = wn * 64 + nt * 8 + ec;
                        *(float2*)(out + r0 * KDIM + col) =
                            make_float2(acc[mt][nt][0], acc[mt][nt][1]);
                        *(float2*)(out + (r0 + 8) * KDIM + col) =
                            make_float2(acc[mt][nt][2], acc[mt][nt][3]);
                    }
                }
#pragma unroll
                for (int mt = 0; mt < 4; mt++)
#pragma unroll
                    for (int nt = 0; nt < 8; nt++)
#pragma unroll
                        for (int i = 0; i < 4; i++) acc[mt][nt][i] = 0.f;
                if (!more) break;
                cur = nxt;
            }
            __syncthreads();            // stage (st^1) ready / WAR guard
            st ^= 1;
            c = (c + 1) & 3;
        }
    }

    // ---- self-resetting counters for graph replays ----
    if (tid == 0) {
        __threadfence();
        unsigned d = atomicAdd(&g_done, 1u);
        if (d == gridDim.x - 1) {       // last CTA: all grabs complete
            g_ctr  = 0u;
            g_done = 0u;
            __threadfence();
        }
    }
}

extern "C" void kernel_launch(void* const* d_in, const int* in_sizes, int n_in,
                              void* d_out, int out_size) {
    const float* x = (const float*)d_in[0];
    const float* W = (const float*)d_in[1];
    float* out = (float*)d_out;

    const int M  = in_sizes[0] / KDIM;   // 401408
    const int NT = M / BM;               // 3136 tiles

    int nsm = 0;
    cudaDeviceGetAttribute(&nsm, cudaDevAttrMultiProcessorCount, 0);
    if (nsm <= 0) nsm = 148;
    if (nsm > NT) nsm = NT;

    cudaFuncSetAttribute(cp2d_fp16_kernel,
                         cudaFuncAttributeMaxDynamicSharedMemorySize, SMEM_TOTAL);

    cp2d_fp16_kernel<<<nsm, 256, SMEM_TOTAL>>>(x, W, out, NT);
}